// round 2
// baseline (speedup 1.0000x reference)
#include <cuda_runtime.h>
#include <cuda_bf16.h>
#include <cstdint>
#include <cstddef>

#define N_NODES 50000
#define N_EDGES 800000
#define IN_DIM  100
#define HID     128
#define BN_EPS  1e-5f

// ---------------------------------------------------------------------------
// Scratch (device globals; no allocations allowed)
// ---------------------------------------------------------------------------
__device__ float g_agg0[N_NODES * IN_DIM];   // layer0 neighbor-sum
__device__ float g_cnt [N_NODES];            // in-degree (float)
__device__ float g_z0  [N_NODES * HID];      // layer0 pre-BN
__device__ float g_h   [N_NODES * HID];      // layer0 post BN+ReLU
__device__ float g_agg1[N_NODES * HID];      // layer1 neighbor-sum
__device__ float g_z1  [N_NODES * HID];      // layer1 pre-BN
__device__ float g_stats [512];              // [L*256 + {sum[128], sumsq[128]}]
__device__ float g_affine[512];              // [L*256 + {scale[128], shift[128]}]

// ---------------------------------------------------------------------------
// Zero scratch accumulators (runs every replay; part of the graph)
// ---------------------------------------------------------------------------
__global__ void zero_all() {
    int i0 = blockIdx.x * blockDim.x + threadIdx.x;
    int stride = gridDim.x * blockDim.x;
    for (int i = i0; i < N_NODES * IN_DIM; i += stride) g_agg0[i] = 0.f;
    for (int i = i0; i < N_NODES * HID;    i += stride) g_agg1[i] = 0.f;
    for (int i = i0; i < N_NODES;          i += stride) g_cnt[i]  = 0.f;
    for (int i = i0; i < 512;              i += stride) g_stats[i] = 0.f;
}

// ---------------------------------------------------------------------------
// Layer-0 scatter: warp per edge, 100 feats across lanes + degree count
// ---------------------------------------------------------------------------
__global__ void scatter0(const float* __restrict__ x, const int* __restrict__ ei) {
    int w = (blockIdx.x * blockDim.x + threadIdx.x) >> 5;
    if (w >= N_EDGES) return;
    int lane = threadIdx.x & 31;
    int src = ei[w];
    int dst = ei[N_EDGES + w];
    const float* xr = x + (size_t)src * IN_DIM;
    float* ar = g_agg0 + (size_t)dst * IN_DIM;
    #pragma unroll
    for (int f = lane; f < IN_DIM; f += 32) atomicAdd(&ar[f], xr[f]);
    if (lane == 0) atomicAdd(&g_cnt[dst], 1.0f);
}

// ---------------------------------------------------------------------------
// Layer-1 scatter: warp per edge, float4 gather of h row (512B coalesced)
// ---------------------------------------------------------------------------
__global__ void scatter1(const int* __restrict__ ei) {
    int w = (blockIdx.x * blockDim.x + threadIdx.x) >> 5;
    if (w >= N_EDGES) return;
    int lane = threadIdx.x & 31;
    int src = ei[w];
    int dst = ei[N_EDGES + w];
    float4 v = *reinterpret_cast<const float4*>(g_h + (size_t)src * HID + lane * 4);
    float* a = g_agg1 + (size_t)dst * HID + lane * 4;
    atomicAdd(a + 0, v.x);
    atomicAdd(a + 1, v.y);
    atomicAdd(a + 2, v.z);
    atomicAdd(a + 3, v.w);
}

// ---------------------------------------------------------------------------
// Fused dual-GEMM per layer:
//   Z[n,:] = (agg[n,:] / max(cnt,1)) @ W_l + b + root[n,:] @ W_r
// Tile: 64 nodes x 128 cols per 256-thread block, K in chunks of 32.
// Thread tile: 8 nodes x 4 contiguous cols.
// ---------------------------------------------------------------------------
constexpr int TM = 64;
constexpr int TK = 32;

template <int L>
__global__ void __launch_bounds__(256) gemm_fused(
    const float* __restrict__ Xin,
    const float* __restrict__ W1,   // [K1][128] neighbor weight
    const float* __restrict__ W2,   // [K2][128] root weight
    const float* __restrict__ bias) // [128]
{
    constexpr int K1 = (L == 0) ? IN_DIM : HID;
    constexpr int K2 = K1;
    constexpr int KT = K1 + K2;
    const float* __restrict__ A1 = (L == 0) ? g_agg0 : g_agg1;
    const float* __restrict__ A2 = (L == 0) ? Xin    : g_h;
    float* __restrict__ Z        = (L == 0) ? g_z0   : g_z1;

    __shared__ float As[TK][TM + 1];
    __shared__ float Ws[TK][HID];
    __shared__ float invs[TM];

    const int tid = threadIdx.x;
    const int nb  = blockIdx.x * TM;

    if (tid < TM) {
        int n = nb + tid;
        float c = (n < N_NODES) ? g_cnt[n] : 1.0f;
        invs[tid] = 1.0f / fmaxf(c, 1.0f);
    }
    __syncthreads();

    const int c4 = (tid & 31) * 4;      // 4 contiguous output cols
    const int ng = (tid >> 5) * 8;      // 8 nodes

    float acc[8][4];
    #pragma unroll
    for (int i = 0; i < 8; i++)
        #pragma unroll
        for (int j = 0; j < 4; j++) acc[i][j] = 0.f;

    for (int k0 = 0; k0 < KT; k0 += TK) {
        // -- load W chunk (coalesced) --
        #pragma unroll
        for (int t = tid; t < TK * HID; t += 256) {
            int kk = t >> 7, c = t & 127;
            int k = k0 + kk;
            float w = 0.f;
            if (k < K1)      w = W1[(size_t)k * HID + c];
            else if (k < KT) w = W2[(size_t)(k - K1) * HID + c];
            Ws[kk][c] = w;
        }
        // -- load A chunk (warp reads 32 consecutive k of one node) --
        #pragma unroll
        for (int t = tid; t < TM * TK; t += 256) {
            int ni = t >> 5, kk = t & 31;
            int n = nb + ni, k = k0 + kk;
            float a = 0.f;
            if (n < N_NODES) {
                if (k < K1)      a = A1[(size_t)n * K1 + k] * invs[ni];
                else if (k < KT) a = A2[(size_t)n * K2 + (k - K1)];
            }
            As[kk][ni] = a;
        }
        __syncthreads();

        #pragma unroll
        for (int kk = 0; kk < TK; kk++) {
            float4 wv = *reinterpret_cast<const float4*>(&Ws[kk][c4]);
            float av[8];
            #pragma unroll
            for (int i = 0; i < 8; i++) av[i] = As[kk][ng + i];
            #pragma unroll
            for (int i = 0; i < 8; i++) {
                acc[i][0] = fmaf(av[i], wv.x, acc[i][0]);
                acc[i][1] = fmaf(av[i], wv.y, acc[i][1]);
                acc[i][2] = fmaf(av[i], wv.z, acc[i][2]);
                acc[i][3] = fmaf(av[i], wv.w, acc[i][3]);
            }
        }
        __syncthreads();
    }

    float4 bv = *reinterpret_cast<const float4*>(&bias[c4]);
    #pragma unroll
    for (int i = 0; i < 8; i++) {
        int n = nb + ng + i;
        if (n < N_NODES) {
            float4 o;
            o.x = acc[i][0] + bv.x;
            o.y = acc[i][1] + bv.y;
            o.z = acc[i][2] + bv.z;
            o.w = acc[i][3] + bv.w;
            *reinterpret_cast<float4*>(&Z[(size_t)n * HID + c4]) = o;
        }
    }
}

// ---------------------------------------------------------------------------
// BN stats: per-column sum / sumsq with block partials + atomics
// ---------------------------------------------------------------------------
template <int L>
__global__ void bn_stats() {
    const float* __restrict__ Z = (L == 0) ? g_z0 : g_z1;
    float* st = g_stats + L * 256;
    int c   = threadIdx.x & 127;
    int sub = threadIdx.x >> 7;               // 0..1 (256 threads)
    int rstep = gridDim.x * 2;
    float s = 0.f, q = 0.f;
    #pragma unroll 4
    for (int r = blockIdx.x * 2 + sub; r < N_NODES; r += rstep) {
        float v = Z[(size_t)r * HID + c];
        s += v;
        q = fmaf(v, v, q);
    }
    atomicAdd(&st[c], s);
    atomicAdd(&st[128 + c], q);
}

template <int L>
__global__ void bn_finalize(const float* __restrict__ gamma,
                            const float* __restrict__ beta) {
    int c = threadIdx.x;
    float s = g_stats[L * 256 + c];
    float q = g_stats[L * 256 + 128 + c];
    float mean = s * (1.0f / N_NODES);
    float var  = q * (1.0f / N_NODES) - mean * mean;
    float sc   = gamma[c] * rsqrtf(var + BN_EPS);
    float sh   = beta[c] - mean * sc;
    g_affine[L * 256 + c]       = sc;
    g_affine[L * 256 + 128 + c] = sh;
}

// h = relu(z0 * scale + shift)
__global__ void apply0() {
    int i0 = blockIdx.x * blockDim.x + threadIdx.x;
    int stride = gridDim.x * blockDim.x;
    for (int i = i0; i < N_NODES * HID; i += stride) {
        int c = i & 127;
        g_h[i] = fmaxf(fmaf(g_z0[i], g_affine[c], g_affine[128 + c]), 0.f);
    }
}

// out = z1 * scale + shift  (no relu)
__global__ void apply_out(float* __restrict__ out) {
    int i0 = blockIdx.x * blockDim.x + threadIdx.x;
    int stride = gridDim.x * blockDim.x;
    for (int i = i0; i < N_NODES * HID; i += stride) {
        int c = i & 127;
        out[i] = fmaf(g_z1[i], g_affine[256 + c], g_affine[384 + c]);
    }
}

// ---------------------------------------------------------------------------
// Launch
// Inputs (metadata order): 0:x 1:edge_index 2:W_l0 3:b_l0 4:W_r0 5:gamma0
//                          6:beta0 7:W_l1 8:b_l1 9:W_r1 10:gamma1 11:beta1
// ---------------------------------------------------------------------------
extern "C" void kernel_launch(void* const* d_in, const int* in_sizes, int n_in,
                              void* d_out, int out_size) {
    const float* x      = (const float*)d_in[0];
    const int*   ei     = (const int*)  d_in[1];
    const float* W_l0   = (const float*)d_in[2];
    const float* b_l0   = (const float*)d_in[3];
    const float* W_r0   = (const float*)d_in[4];
    const float* gamma0 = (const float*)d_in[5];
    const float* beta0  = (const float*)d_in[6];
    const float* W_l1   = (const float*)d_in[7];
    const float* b_l1   = (const float*)d_in[8];
    const float* W_r1   = (const float*)d_in[9];
    const float* gamma1 = (const float*)d_in[10];
    const float* beta1  = (const float*)d_in[11];
    float* out = (float*)d_out;

    const int scatter_blocks = (N_EDGES * 32 + 255) / 256;   // warp per edge
    const int gemm_blocks    = (N_NODES + TM - 1) / TM;

    zero_all<<<2048, 256>>>();

    // Layer 0
    scatter0<<<scatter_blocks, 256>>>(x, ei);
    gemm_fused<0><<<gemm_blocks, 256>>>(x, W_l0, W_r0, b_l0);
    bn_stats<0><<<512, 256>>>();
    bn_finalize<0><<<1, 128>>>(gamma0, beta0);
    apply0<<<4096, 256>>>();

    // Layer 1
    scatter1<<<scatter_blocks, 256>>>(ei);
    gemm_fused<1><<<gemm_blocks, 256>>>(nullptr, W_l1, W_r1, b_l1);
    bn_stats<1><<<512, 256>>>();
    bn_finalize<1><<<1, 128>>>(gamma1, beta1);
    apply_out<<<4096, 256>>>(out);
}

// round 8
// speedup vs baseline: 1.4971x; 1.4971x over previous
#include <cuda_runtime.h>
#include <cuda_bf16.h>
#include <cstdint>
#include <cstddef>

#define N_NODES 50000
#define N_EDGES 800000
#define IN_DIM  100
#define HID     128
#define BN_EPS  1e-5f

// ---------------------------------------------------------------------------
// Scratch (device globals; referenced ONLY inside device code)
// ---------------------------------------------------------------------------
__device__ int   g_deg   [N_NODES];
__device__ int   g_off   [N_NODES];
__device__ int   g_cursor[N_NODES];
__device__ int   g_csr   [N_EDGES];          // src ids grouped by dst
__device__ float g_yl[N_NODES * HID];        // x @ W_l  (to be gathered)
__device__ float g_yr[N_NODES * HID];        // x @ W_r + b (root path)
__device__ float g_z [N_NODES * HID];        // pre-BN (reused both layers)
__device__ float g_h [N_NODES * HID];        // layer0 post BN+ReLU
__device__ float g_stats [512];              // [L*256 + {sum[128], sumsq[128]}]
__device__ float g_affine[512];              // [L*256 + {scale[128], shift[128]}]

// ---------------------------------------------------------------------------
// Zero small accumulators (part of the graph, every replay)
// ---------------------------------------------------------------------------
__global__ void zero_small() {
    int i = blockIdx.x * blockDim.x + threadIdx.x;
    if (i < N_NODES) g_deg[i] = 0;
    if (i < 512)     g_stats[i] = 0.f;
}

// ---------------------------------------------------------------------------
// CSR build: histogram -> 1-block scan -> cursor fill
// ---------------------------------------------------------------------------
__global__ void csr_hist(const int* __restrict__ ei) {
    int e = blockIdx.x * blockDim.x + threadIdx.x;
    if (e >= N_EDGES) return;
    atomicAdd(&g_deg[ei[N_EDGES + e]], 1);
}

__global__ void __launch_bounds__(1024) csr_scan() {
    __shared__ int sh[1024];
    const int CH = 49;                       // 1024*49 = 50176 >= N_NODES
    int t = threadIdx.x;
    int base = t * CH;
    int s = 0;
    #pragma unroll 7
    for (int i = 0; i < CH; i++) {
        int idx = base + i;
        if (idx < N_NODES) s += g_deg[idx];
    }
    sh[t] = s;
    __syncthreads();
    #pragma unroll
    for (int d = 1; d < 1024; d <<= 1) {
        int v = (t >= d) ? sh[t - d] : 0;
        __syncthreads();
        sh[t] += v;
        __syncthreads();
    }
    int run = (t == 0) ? 0 : sh[t - 1];
    #pragma unroll 7
    for (int i = 0; i < CH; i++) {
        int idx = base + i;
        if (idx < N_NODES) {
            g_off[idx]    = run;
            g_cursor[idx] = run;
            run += g_deg[idx];
        }
    }
}

__global__ void csr_fill(const int* __restrict__ ei) {
    int e = blockIdx.x * blockDim.x + threadIdx.x;
    if (e >= N_EDGES) return;
    int src = ei[e];
    int dst = ei[N_EDGES + e];
    int pos = atomicAdd(&g_cursor[dst], 1);
    g_csr[pos] = src;
}

// ---------------------------------------------------------------------------
// GEMM: Out[n, 0:128] = A[n, 0:K] @ W   (f32x2 packed FMA micro-kernel)
// 64-node x 128-col tile, 256 threads, thread tile 8 rows x 4 cols.
// blockIdx.y: 0 -> W_l -> g_yl (no bias), 1 -> W_r -> g_yr (+bias)
// L=0: A = x (kernel arg). L=1: A = g_h (device global, bound in device code).
// ---------------------------------------------------------------------------
template <int L>
__global__ void __launch_bounds__(256) gemm128(
    const float* __restrict__ Xin,
    const float* __restrict__ Wl, const float* __restrict__ Wr,
    const float* __restrict__ bias)
{
    constexpr int K = (L == 0) ? IN_DIM : HID;
    const float* __restrict__ A   = (L == 0) ? Xin : g_h;
    const float* __restrict__ W   = blockIdx.y ? Wr   : Wl;
    float* __restrict__       Out = blockIdx.y ? g_yr : g_yl;

    __shared__ __align__(16) float As[32][65];   // [k][node]
    __shared__ __align__(16) float Ws[32][128];  // [k][col]

    const int tid = threadIdx.x;
    const int nb  = blockIdx.x * 64;
    const int c4  = (tid & 31) * 4;   // 4 contiguous output cols
    const int ng  = (tid >> 5) * 8;   // 8 rows

    unsigned long long acc2[8][2];
    #pragma unroll
    for (int i = 0; i < 8; i++) { acc2[i][0] = 0ull; acc2[i][1] = 0ull; }

    for (int k0 = 0; k0 < K; k0 += 32) {
        #pragma unroll
        for (int t = tid; t < 32 * 128; t += 256) {
            int kk = t >> 7, c = t & 127;
            int k = k0 + kk;
            Ws[kk][c] = (k < K) ? W[(size_t)k * 128 + c] : 0.f;
        }
        #pragma unroll
        for (int t = tid; t < 64 * 32; t += 256) {
            int ni = t >> 5, kk = t & 31;
            int n = nb + ni, k = k0 + kk;
            As[kk][ni] = (n < N_NODES && k < K) ? A[(size_t)n * K + k] : 0.f;
        }
        __syncthreads();

        #pragma unroll
        for (int kk = 0; kk < 32; kk++) {
            ulonglong2 w2 = *reinterpret_cast<const ulonglong2*>(&Ws[kk][c4]);
            #pragma unroll
            for (int i = 0; i < 8; i++) {
                float a = As[kk][ng + i];
                unsigned long long a2;
                asm("mov.b64 %0, {%1, %1};" : "=l"(a2) : "f"(a));
                asm("fma.rn.f32x2 %0, %1, %2, %0;" : "+l"(acc2[i][0]) : "l"(a2), "l"(w2.x));
                asm("fma.rn.f32x2 %0, %1, %2, %0;" : "+l"(acc2[i][1]) : "l"(a2), "l"(w2.y));
            }
        }
        __syncthreads();
    }

    float4 bv = make_float4(0.f, 0.f, 0.f, 0.f);
    if (blockIdx.y) bv = *reinterpret_cast<const float4*>(&bias[c4]);
    #pragma unroll
    for (int i = 0; i < 8; i++) {
        int n = nb + ng + i;
        if (n < N_NODES) {
            float2 lo = *reinterpret_cast<float2*>(&acc2[i][0]);
            float2 hi = *reinterpret_cast<float2*>(&acc2[i][1]);
            float4 o = make_float4(lo.x + bv.x, lo.y + bv.y, hi.x + bv.z, hi.y + bv.w);
            *reinterpret_cast<float4*>(&Out[(size_t)n * 128 + c4]) = o;
        }
    }
}

// ---------------------------------------------------------------------------
// Gather: g_z[n,f] = (sum_{j in N(n)} g_yl[j,f]) / max(deg,1) + g_yr[n,f]
// 2 nodes per 256-thread block, 128 threads per node, coalesced row reads.
// ---------------------------------------------------------------------------
__global__ void __launch_bounds__(256) gather() {
    int node = blockIdx.x * 2 + (threadIdx.x >> 7);
    if (node >= N_NODES) return;
    int f   = threadIdx.x & 127;
    int off = g_off[node];
    int deg = g_deg[node];

    float s0 = 0.f, s1 = 0.f, s2 = 0.f, s3 = 0.f;
    int e = 0;
    for (; e + 4 <= deg; e += 4) {
        int i0 = g_csr[off + e + 0];
        int i1 = g_csr[off + e + 1];
        int i2 = g_csr[off + e + 2];
        int i3 = g_csr[off + e + 3];
        s0 += g_yl[(size_t)i0 * 128 + f];
        s1 += g_yl[(size_t)i1 * 128 + f];
        s2 += g_yl[(size_t)i2 * 128 + f];
        s3 += g_yl[(size_t)i3 * 128 + f];
    }
    for (; e < deg; e++) s0 += g_yl[(size_t)g_csr[off + e] * 128 + f];

    float s   = (s0 + s1) + (s2 + s3);
    float inv = 1.f / fmaxf((float)deg, 1.f);
    g_z[(size_t)node * 128 + f] = fmaf(s, inv, g_yr[(size_t)node * 128 + f]);
}

// ---------------------------------------------------------------------------
// BatchNorm: column stats + fold into scale/shift
// ---------------------------------------------------------------------------
template <int L>
__global__ void bn_stats() {
    float* st = g_stats + L * 256;
    int c   = threadIdx.x & 127;
    int sub = threadIdx.x >> 7;
    int rstep = gridDim.x * 2;
    float s = 0.f, q = 0.f;
    #pragma unroll 4
    for (int r = blockIdx.x * 2 + sub; r < N_NODES; r += rstep) {
        float v = g_z[(size_t)r * HID + c];
        s += v;
        q = fmaf(v, v, q);
    }
    atomicAdd(&st[c], s);
    atomicAdd(&st[128 + c], q);
}

template <int L>
__global__ void bn_finalize(const float* __restrict__ gamma,
                            const float* __restrict__ beta) {
    int c = threadIdx.x;
    float s = g_stats[L * 256 + c];
    float q = g_stats[L * 256 + 128 + c];
    float mean = s * (1.0f / N_NODES);
    float var  = q * (1.0f / N_NODES) - mean * mean;
    float sc   = gamma[c] * rsqrtf(var + BN_EPS);
    float sh   = beta[c] - mean * sc;
    g_affine[L * 256 + c]       = sc;
    g_affine[L * 256 + 128 + c] = sh;
}

// h = relu(z * scale + shift)
__global__ void apply0() {
    int i0 = blockIdx.x * blockDim.x + threadIdx.x;
    int stride = gridDim.x * blockDim.x;
    for (int i = i0; i < N_NODES * HID; i += stride) {
        int c = i & 127;
        g_h[i] = fmaxf(fmaf(g_z[i], g_affine[c], g_affine[128 + c]), 0.f);
    }
}

// out = z * scale + shift
__global__ void apply_out(float* __restrict__ out) {
    int i0 = blockIdx.x * blockDim.x + threadIdx.x;
    int stride = gridDim.x * blockDim.x;
    for (int i = i0; i < N_NODES * HID; i += stride) {
        int c = i & 127;
        out[i] = fmaf(g_z[i], g_affine[256 + c], g_affine[384 + c]);
    }
}

// ---------------------------------------------------------------------------
// Launch
// Inputs: 0:x 1:edge_index 2:W_l0 3:b_l0 4:W_r0 5:gamma0 6:beta0
//         7:W_l1 8:b_l1 9:W_r1 10:gamma1 11:beta1
// ---------------------------------------------------------------------------
extern "C" void kernel_launch(void* const* d_in, const int* in_sizes, int n_in,
                              void* d_out, int out_size) {
    const float* x      = (const float*)d_in[0];
    const int*   ei     = (const int*)  d_in[1];
    const float* W_l0   = (const float*)d_in[2];
    const float* b_l0   = (const float*)d_in[3];
    const float* W_r0   = (const float*)d_in[4];
    const float* gamma0 = (const float*)d_in[5];
    const float* beta0  = (const float*)d_in[6];
    const float* W_l1   = (const float*)d_in[7];
    const float* b_l1   = (const float*)d_in[8];
    const float* W_r1   = (const float*)d_in[9];
    const float* gamma1 = (const float*)d_in[10];
    const float* beta1  = (const float*)d_in[11];
    float* out = (float*)d_out;

    const int edge_blocks = (N_EDGES + 255) / 256;
    const int gemm_blocks = (N_NODES + 63) / 64;

    zero_small<<<(N_NODES + 255) / 256, 256>>>();
    csr_hist<<<edge_blocks, 256>>>(ei);
    csr_scan<<<1, 1024>>>();
    csr_fill<<<edge_blocks, 256>>>(ei);

    // Layer 0: yl = x@W_l0, yr = x@W_r0 + b_l0; z = gather(yl)/deg + yr
    gemm128<0><<<dim3(gemm_blocks, 2), 256>>>(x, W_l0, W_r0, b_l0);
    gather<<<(N_NODES + 1) / 2, 256>>>();
    bn_stats<0><<<512, 256>>>();
    bn_finalize<0><<<1, 128>>>(gamma0, beta0);
    apply0<<<2048, 256>>>();

    // Layer 1
    gemm128<1><<<dim3(gemm_blocks, 2), 256>>>(x, W_l1, W_r1, b_l1);
    gather<<<(N_NODES + 1) / 2, 256>>>();
    bn_stats<1><<<512, 256>>>();
    bn_finalize<1><<<1, 128>>>(gamma1, beta1);
    apply_out<<<2048, 256>>>(out);
}

// round 9
// speedup vs baseline: 1.5930x; 1.0641x over previous
#include <cuda_runtime.h>
#include <cuda_bf16.h>
#include <cstdint>
#include <cstddef>

#define N_NODES 50000
#define N_EDGES 800000
#define IN_DIM  100
#define HID     128
#define BN_EPS  1e-5f

// ---------------------------------------------------------------------------
// Scratch (device globals; referenced ONLY inside device code)
// ---------------------------------------------------------------------------
__device__ int   g_deg   [N_NODES];
__device__ int   g_off   [N_NODES];
__device__ int   g_cursor[N_NODES];
__device__ int   g_csr   [N_EDGES];          // src ids grouped by dst
__device__ float g_yl[N_NODES * HID];        // A @ W_l  (to be gathered)
__device__ float g_yr[N_NODES * HID];        // A @ W_r + b (root path)
__device__ float g_z [N_NODES * HID];        // layer0 pre-BN
__device__ float g_z2[N_NODES * HID];        // layer1 pre-BN
__device__ float g_stats [512];              // [L*256 + {sum[128], sumsq[128]}]
__device__ float g_affine[512];              // [L*256 + {scale[128], shift[128]}]

// ---------------------------------------------------------------------------
// Zero small accumulators (part of the graph, every replay)
// ---------------------------------------------------------------------------
__global__ void zero_small() {
    int i = blockIdx.x * blockDim.x + threadIdx.x;
    if (i < N_NODES) g_deg[i] = 0;
    if (i < 512)     g_stats[i] = 0.f;
}

// ---------------------------------------------------------------------------
// CSR build: histogram -> 1-block scan -> cursor fill
// ---------------------------------------------------------------------------
__global__ void csr_hist(const int* __restrict__ ei) {
    int e = blockIdx.x * blockDim.x + threadIdx.x;
    if (e >= N_EDGES) return;
    atomicAdd(&g_deg[ei[N_EDGES + e]], 1);
}

__global__ void __launch_bounds__(1024) csr_scan() {
    __shared__ int sh[1024];
    const int CH = 49;                       // 1024*49 = 50176 >= N_NODES
    int t = threadIdx.x;
    int base = t * CH;
    int s = 0;
    #pragma unroll 7
    for (int i = 0; i < CH; i++) {
        int idx = base + i;
        if (idx < N_NODES) s += g_deg[idx];
    }
    sh[t] = s;
    __syncthreads();
    #pragma unroll
    for (int d = 1; d < 1024; d <<= 1) {
        int v = (t >= d) ? sh[t - d] : 0;
        __syncthreads();
        sh[t] += v;
        __syncthreads();
    }
    int run = (t == 0) ? 0 : sh[t - 1];
    #pragma unroll 7
    for (int i = 0; i < CH; i++) {
        int idx = base + i;
        if (idx < N_NODES) {
            g_off[idx]    = run;
            g_cursor[idx] = run;
            run += g_deg[idx];
        }
    }
}

__global__ void csr_fill(const int* __restrict__ ei) {
    int e = blockIdx.x * blockDim.x + threadIdx.x;
    if (e >= N_EDGES) return;
    int src = ei[e];
    int dst = ei[N_EDGES + e];
    int pos = atomicAdd(&g_cursor[dst], 1);
    g_csr[pos] = src;
}

// ---------------------------------------------------------------------------
// GEMM: Out[n, 0:128] = A[n, 0:K] @ W   (f32x2 packed FMA, 8x8 thread tile)
// Block tile: 128 nodes x 128 cols, 256 threads, K chunks of 32.
// blockIdx.y: 0 -> W_l -> g_yl (no bias), 1 -> W_r -> g_yr (+bias)
// L=0: A = x (arg).  L=1: A = relu(g_z * affine0_scale + affine0_shift).
// ---------------------------------------------------------------------------
template <int L>
__global__ void __launch_bounds__(256) gemm128(
    const float* __restrict__ Xin,
    const float* __restrict__ Wl, const float* __restrict__ Wr,
    const float* __restrict__ bias)
{
    constexpr int K = (L == 0) ? IN_DIM : HID;
    const float* __restrict__ A   = (L == 0) ? Xin : g_z;
    const float* __restrict__ W   = blockIdx.y ? Wr   : Wl;
    float* __restrict__       Out = blockIdx.y ? g_yr : g_yl;

    __shared__ __align__(16) float As[32][129];  // [k][node], pad -> conflict-free STS
    __shared__ __align__(16) float Ws[32][128];  // [k][col]
    __shared__ float aff[256];                   // layer0 affine (L==1 only)

    const int tid = threadIdx.x;
    const int nb  = blockIdx.x * 128;
    const int c8  = (tid & 15) * 8;   // 8 contiguous output cols
    const int r8  = (tid >> 4) * 8;   // 8 rows

    if (L == 1) aff[tid] = g_affine[tid];
    if (L == 1) __syncthreads();

    unsigned long long acc2[8][4];
    #pragma unroll
    for (int i = 0; i < 8; i++)
        #pragma unroll
        for (int j = 0; j < 4; j++) acc2[i][j] = 0ull;

    for (int k0 = 0; k0 < K; k0 += 32) {
        #pragma unroll
        for (int t = tid; t < 32 * 128; t += 256) {
            int kk = t >> 7, c = t & 127;
            int k = k0 + kk;
            Ws[kk][c] = (k < K) ? W[(size_t)k * 128 + c] : 0.f;
        }
        #pragma unroll
        for (int t = tid; t < 128 * 32; t += 256) {
            int ni = t >> 5, kk = t & 31;
            int n = nb + ni, k = k0 + kk;
            float a = 0.f;
            if (n < N_NODES && k < K) {
                a = A[(size_t)n * K + k];
                if (L == 1) a = fmaxf(fmaf(a, aff[k], aff[128 + k]), 0.f);
            }
            As[kk][ni] = a;
        }
        __syncthreads();

        #pragma unroll
        for (int kk = 0; kk < 32; kk++) {
            ulonglong2 w01 = *reinterpret_cast<const ulonglong2*>(&Ws[kk][c8]);
            ulonglong2 w23 = *reinterpret_cast<const ulonglong2*>(&Ws[kk][c8 + 4]);
            #pragma unroll
            for (int i = 0; i < 8; i++) {
                float a = As[kk][r8 + i];
                unsigned long long a2;
                asm("mov.b64 %0, {%1, %1};" : "=l"(a2) : "f"(a));
                asm("fma.rn.f32x2 %0, %1, %2, %0;" : "+l"(acc2[i][0]) : "l"(a2), "l"(w01.x));
                asm("fma.rn.f32x2 %0, %1, %2, %0;" : "+l"(acc2[i][1]) : "l"(a2), "l"(w01.y));
                asm("fma.rn.f32x2 %0, %1, %2, %0;" : "+l"(acc2[i][2]) : "l"(a2), "l"(w23.x));
                asm("fma.rn.f32x2 %0, %1, %2, %0;" : "+l"(acc2[i][3]) : "l"(a2), "l"(w23.y));
            }
        }
        __syncthreads();
    }

    float4 bv0 = make_float4(0.f, 0.f, 0.f, 0.f);
    float4 bv1 = make_float4(0.f, 0.f, 0.f, 0.f);
    if (blockIdx.y) {
        bv0 = *reinterpret_cast<const float4*>(&bias[c8]);
        bv1 = *reinterpret_cast<const float4*>(&bias[c8 + 4]);
    }
    #pragma unroll
    for (int i = 0; i < 8; i++) {
        int n = nb + r8 + i;
        if (n < N_NODES) {
            float2 p0 = *reinterpret_cast<float2*>(&acc2[i][0]);
            float2 p1 = *reinterpret_cast<float2*>(&acc2[i][1]);
            float2 p2 = *reinterpret_cast<float2*>(&acc2[i][2]);
            float2 p3 = *reinterpret_cast<float2*>(&acc2[i][3]);
            float4 o0 = make_float4(p0.x + bv0.x, p0.y + bv0.y, p1.x + bv0.z, p1.y + bv0.w);
            float4 o1 = make_float4(p2.x + bv1.x, p2.y + bv1.y, p3.x + bv1.z, p3.y + bv1.w);
            *reinterpret_cast<float4*>(&Out[(size_t)n * 128 + c8])     = o0;
            *reinterpret_cast<float4*>(&Out[(size_t)n * 128 + c8 + 4]) = o1;
        }
    }
}

// ---------------------------------------------------------------------------
// Gather: z[n,f] = (sum_{j in N(n)} yl[j,f]) / max(deg,1) + yr[n,f]
// One warp per node; lane owns 16B (float4) of the 512B row. CSR indices
// broadcast-loaded; unroll 4 for MLP.
// L selects destination buffer (g_z layer0, g_z2 layer1).
// ---------------------------------------------------------------------------
template <int L>
__global__ void __launch_bounds__(256) gather() {
    int node = (blockIdx.x * 256 + threadIdx.x) >> 5;
    if (node >= N_NODES) return;
    int lane = threadIdx.x & 31;
    int off  = g_off[node];
    int deg  = g_deg[node];
    float* __restrict__ Z = (L == 0) ? g_z : g_z2;

    float4 s0 = make_float4(0.f, 0.f, 0.f, 0.f);
    float4 s1 = make_float4(0.f, 0.f, 0.f, 0.f);
    float4 s2 = make_float4(0.f, 0.f, 0.f, 0.f);
    float4 s3 = make_float4(0.f, 0.f, 0.f, 0.f);

    const size_t fo = (size_t)lane * 4;
    int e = 0;
    for (; e + 4 <= deg; e += 4) {
        int i0 = g_csr[off + e + 0];
        int i1 = g_csr[off + e + 1];
        int i2 = g_csr[off + e + 2];
        int i3 = g_csr[off + e + 3];
        float4 v0 = *reinterpret_cast<const float4*>(&g_yl[(size_t)i0 * 128 + fo]);
        float4 v1 = *reinterpret_cast<const float4*>(&g_yl[(size_t)i1 * 128 + fo]);
        float4 v2 = *reinterpret_cast<const float4*>(&g_yl[(size_t)i2 * 128 + fo]);
        float4 v3 = *reinterpret_cast<const float4*>(&g_yl[(size_t)i3 * 128 + fo]);
        s0.x += v0.x; s0.y += v0.y; s0.z += v0.z; s0.w += v0.w;
        s1.x += v1.x; s1.y += v1.y; s1.z += v1.z; s1.w += v1.w;
        s2.x += v2.x; s2.y += v2.y; s2.z += v2.z; s2.w += v2.w;
        s3.x += v3.x; s3.y += v3.y; s3.z += v3.z; s3.w += v3.w;
    }
    for (; e < deg; e++) {
        int j = g_csr[off + e];
        float4 v = *reinterpret_cast<const float4*>(&g_yl[(size_t)j * 128 + fo]);
        s0.x += v.x; s0.y += v.y; s0.z += v.z; s0.w += v.w;
    }

    float inv = 1.f / fmaxf((float)deg, 1.f);
    float4 r = *reinterpret_cast<const float4*>(&g_yr[(size_t)node * 128 + fo]);
    float4 o;
    o.x = fmaf((s0.x + s1.x) + (s2.x + s3.x), inv, r.x);
    o.y = fmaf((s0.y + s1.y) + (s2.y + s3.y), inv, r.y);
    o.z = fmaf((s0.z + s1.z) + (s2.z + s3.z), inv, r.z);
    o.w = fmaf((s0.w + s1.w) + (s2.w + s3.w), inv, r.w);
    *reinterpret_cast<float4*>(&Z[(size_t)node * 128 + fo]) = o;
}

// ---------------------------------------------------------------------------
// BatchNorm: column stats + fold into scale/shift
// ---------------------------------------------------------------------------
template <int L>
__global__ void bn_stats() {
    const float* __restrict__ Z = (L == 0) ? g_z : g_z2;
    float* st = g_stats + L * 256;
    int c   = threadIdx.x & 127;
    int sub = threadIdx.x >> 7;
    int rstep = gridDim.x * 2;
    float s = 0.f, q = 0.f;
    #pragma unroll 4
    for (int r = blockIdx.x * 2 + sub; r < N_NODES; r += rstep) {
        float v = Z[(size_t)r * HID + c];
        s += v;
        q = fmaf(v, v, q);
    }
    atomicAdd(&st[c], s);
    atomicAdd(&st[128 + c], q);
}

template <int L>
__global__ void bn_finalize(const float* __restrict__ gamma,
                            const float* __restrict__ beta) {
    int c = threadIdx.x;
    float s = g_stats[L * 256 + c];
    float q = g_stats[L * 256 + 128 + c];
    float mean = s * (1.0f / N_NODES);
    float var  = q * (1.0f / N_NODES) - mean * mean;
    float sc   = gamma[c] * rsqrtf(var + BN_EPS);
    float sh   = beta[c] - mean * sc;
    g_affine[L * 256 + c]       = sc;
    g_affine[L * 256 + 128 + c] = sh;
}

// out = z2 * scale1 + shift1
__global__ void apply_out(float* __restrict__ out) {
    int i0 = blockIdx.x * blockDim.x + threadIdx.x;
    int stride = gridDim.x * blockDim.x;
    for (int i = i0; i < N_NODES * HID; i += stride) {
        int c = i & 127;
        out[i] = fmaf(g_z2[i], g_affine[256 + c], g_affine[384 + c]);
    }
}

// ---------------------------------------------------------------------------
// Launch
// Inputs: 0:x 1:edge_index 2:W_l0 3:b_l0 4:W_r0 5:gamma0 6:beta0
//         7:W_l1 8:b_l1 9:W_r1 10:gamma1 11:beta1
// ---------------------------------------------------------------------------
extern "C" void kernel_launch(void* const* d_in, const int* in_sizes, int n_in,
                              void* d_out, int out_size) {
    const float* x      = (const float*)d_in[0];
    const int*   ei     = (const int*)  d_in[1];
    const float* W_l0   = (const float*)d_in[2];
    const float* b_l0   = (const float*)d_in[3];
    const float* W_r0   = (const float*)d_in[4];
    const float* gamma0 = (const float*)d_in[5];
    const float* beta0  = (const float*)d_in[6];
    const float* W_l1   = (const float*)d_in[7];
    const float* b_l1   = (const float*)d_in[8];
    const float* W_r1   = (const float*)d_in[9];
    const float* gamma1 = (const float*)d_in[10];
    const float* beta1  = (const float*)d_in[11];
    float* out = (float*)d_out;

    const int edge_blocks   = (N_EDGES + 255) / 256;
    const int gemm_blocks   = (N_NODES + 127) / 128;
    const int gather_blocks = (N_NODES * 32 + 255) / 256;   // warp per node

    zero_small<<<(N_NODES + 255) / 256, 256>>>();
    csr_hist<<<edge_blocks, 256>>>(ei);
    csr_scan<<<1, 1024>>>();
    csr_fill<<<edge_blocks, 256>>>(ei);

    // Layer 0
    gemm128<0><<<dim3(gemm_blocks, 2), 256>>>(x, W_l0, W_r0, b_l0);
    gather<0><<<gather_blocks, 256>>>();
    bn_stats<0><<<512, 256>>>();
    bn_finalize<0><<<1, 128>>>(gamma0, beta0);

    // Layer 1 (BN0 + ReLU fused into A-load of gemm128<1>)
    gemm128<1><<<dim3(gemm_blocks, 2), 256>>>(x, W_l1, W_r1, b_l1);
    gather<1><<<gather_blocks, 256>>>();
    bn_stats<1><<<512, 256>>>();
    bn_finalize<1><<<1, 128>>>(gamma1, beta1);
    apply_out<<<2048, 256>>>(out);
}